// round 10
// baseline (speedup 1.0000x reference)
#include <cuda_runtime.h>
#include <cuda_bf16.h>

#define Bb   128
#define DIN  512
#define HH   1024
#define G4   4096
#define TT   256
#define OO   1024
#define BH   (Bb*HH)      // 131072
#define NBLK 128
#define NTHR 256

// ---- device-global scratch ----
__device__ __align__(16) unsigned      g_hpk[(TT+1)*BH];     // packed (hi | lo<<16) bf16 h history
__device__ __align__(16) float         g_c0[BH];             // initial cell state
__device__ __align__(16) unsigned char g_WswF[NBLK*131072];  // folded slices (t>=1), tile layout
__device__ __align__(16) unsigned char g_Wsw0[NBLK*131072];  // W_hh slices (t==0), tile layout
__device__ __align__(16) unsigned char g_WoT[16*16*16384];   // W_out tiles [nb][ch][split][ck4][16x128B]
__device__ float    g_bF[G4];
__device__ float    g_b0[G4];
__device__ unsigned g_flag[(TT+1)*16];                       // per-(step,group) producer flags

__device__ __forceinline__ float sigf(float x) { return 1.0f / (1.0f + __expf(-x)); }

__device__ __forceinline__ unsigned pk_split(float v) {
    __nv_bfloat16 hi = __float2bfloat16(v);
    __nv_bfloat16 lo = __float2bfloat16(v - __bfloat162float(hi));
    return (unsigned)__bfloat16_as_ushort(hi) | ((unsigned)__bfloat16_as_ushort(lo) << 16);
}

__device__ __forceinline__ unsigned smem_u32(const void* p) {
    return (unsigned)__cvta_generic_to_shared(p);
}
__device__ __forceinline__ void ldsm4(unsigned* r, unsigned addr) {
    asm volatile("ldmatrix.sync.aligned.m8n8.x4.shared.b16 {%0,%1,%2,%3}, [%4];"
                 : "=r"(r[0]), "=r"(r[1]), "=r"(r[2]), "=r"(r[3]) : "r"(addr));
}
__device__ __forceinline__ void mma16816(float* d, const unsigned* a, const unsigned* b) {
    asm volatile("mma.sync.aligned.m16n8k16.row.col.f32.bf16.bf16.f32 "
                 "{%0,%1,%2,%3}, {%4,%5,%6,%7}, {%8,%9}, {%0,%1,%2,%3};"
                 : "+f"(d[0]), "+f"(d[1]), "+f"(d[2]), "+f"(d[3])
                 : "r"(a[0]), "r"(a[1]), "r"(a[2]), "r"(a[3]), "r"(b[0]), "r"(b[1]));
}
// acquire spin: orders subsequent h reads after the observed flag value
__device__ __forceinline__ void waitflag(int t, int g) {
    const unsigned* p = &g_flag[t * 16 + g];
    unsigned v;
    do {
        asm volatile("ld.acquire.gpu.global.u32 %0, [%1];" : "=r"(v) : "l"(p) : "memory");
    } while (v < 8u);
}
// release post (producer has already fenced all threads' stores + barrier)
__device__ __forceinline__ void postflag(int t, int g) {
    asm volatile("red.release.gpu.global.add.u32 [%0], %1;"
                 :: "l"(&g_flag[t * 16 + g]), "r"(1u) : "memory");
}

// zero flags (runs before k_steps every launch/replay)
__global__ void k_zero() {
    int i = blockIdx.x * blockDim.x + threadIdx.x;
    if (i < (TT + 1) * 16) g_flag[i] = 0u;
}

// ---------------------------------------------------------------------------
// k_foldw: permute + fold weights into per-block slice tiles (ldmatrix-native).
// Slice row rr (0..31): gate=rr>>3, unit=rr&7 -> j = gate*1024 + blk*8 + unit.
// Tile layout per split (64KB): off = (k>>4)*1024 + ((gate*2)+((k>>3)&1))*128
//                                     + unit*16 + (k&7)*2
// ---------------------------------------------------------------------------
__global__ void k_foldw(const float* __restrict__ Wih, const float* __restrict__ Whh) {
    int i = blockIdx.x * blockDim.x + threadIdx.x;   // 4,194,304
    int k = i & 1023, rr = (i >> 10) & 31, blk = i >> 15;
    int gate = rr >> 3, unit = rr & 7;
    int j = (gate << 10) + (blk << 3) + unit;
    float a = Wih[(size_t)j * HH + k];
    float b = Whh[(size_t)j * HH + k];
    float f = a + b;
    int off = ((k >> 4) << 10) + (((gate << 1) + ((k >> 3) & 1)) << 7) + (unit << 4) + ((k & 7) << 1);
    unsigned char* bF = g_WswF + (size_t)blk * 131072;
    unsigned char* b0 = g_Wsw0 + (size_t)blk * 131072;
    __nv_bfloat16 fh = __float2bfloat16(f);
    __nv_bfloat16 fl = __float2bfloat16(f - __bfloat162float(fh));
    *(__nv_bfloat16*)(bF + off)         = fh;
    *(__nv_bfloat16*)(bF + 65536 + off) = fl;
    __nv_bfloat16 wh = __float2bfloat16(b);
    __nv_bfloat16 wl = __float2bfloat16(b - __bfloat162float(wh));
    *(__nv_bfloat16*)(b0 + off)         = wh;
    *(__nv_bfloat16*)(b0 + 65536 + off) = wl;
}

// W_out -> [nb(16)][ch(16)] 16KB blocks: [split(2)][ck4(4)][nt*2+kt tiles 16x128B]
__global__ void k_foldo(const float* __restrict__ Wout) {
    int i = blockIdx.x * blockDim.x + threadIdx.x;   // 1,048,576
    int k = i & 1023, o = i >> 10;
    int nb = o >> 6, nt = (o >> 3) & 7, r = o & 7;
    int ch = k >> 6, ck4 = (k >> 4) & 3, kt = (k >> 3) & 1, c = k & 7;
    unsigned char* base = g_WoT + (size_t)(nb * 16 + ch) * 16384;
    int toff = (ck4 << 11) + (((nt << 1) + kt) << 7) + (r << 4) + (c << 1);
    float w = Wout[(size_t)o * HH + k];
    __nv_bfloat16 hi = __float2bfloat16(w);
    __nv_bfloat16 lo = __float2bfloat16(w - __bfloat162float(hi));
    *(__nv_bfloat16*)(base + toff)        = hi;
    *(__nv_bfloat16*)(base + 8192 + toff) = lo;
}

// bias fold (perm order r = gate*8+unit per blk)
__global__ void k_bias(const float* __restrict__ Wih, const float* __restrict__ bih,
                       const float* __restrict__ bhh, const float* __restrict__ x0) {
    int w    = (blockIdx.x * blockDim.x + threadIdx.x) >> 5;
    int lane = threadIdx.x & 31;
    if (w >= G4) return;
    int blk = w >> 5, lr = w & 31;
    int j   = (blk << 3) + (lr & 7) + ((lr >> 3) << 10);
    float s = 0.f;
    for (int k = lane; k < HH; k += 32) s += x0[k] * Wih[(size_t)j * HH + k];
    #pragma unroll
    for (int off = 16; off; off >>= 1) s += __shfl_down_sync(0xffffffffu, s, off);
    if (lane == 0) {
        float bf = bih[j] + bhh[j];
        g_bF[w] = bf;
        g_b0[w] = bf + s;
    }
}

// h0 (packed bf16 split) -> g_hpk slot 0 ; c0 -> g_c0
__global__ void k_init(const float* __restrict__ z,
                       const float* __restrict__ Wh, const float* __restrict__ bh,
                       const float* __restrict__ Wc, const float* __restrict__ bc) {
    int w    = (blockIdx.x * blockDim.x + threadIdx.x) >> 5;
    int lane = threadIdx.x & 31;
    int b = w >> 10, u = w & 1023;
    float sh = 0.f, sc = 0.f;
    for (int k = lane; k < DIN; k += 32) {
        float zv = z[b * DIN + k];
        sh += zv * Wh[u * DIN + k];
        sc += zv * Wc[u * DIN + k];
    }
    #pragma unroll
    for (int off = 16; off; off >>= 1) {
        sh += __shfl_down_sync(0xffffffffu, sh, off);
        sc += __shfl_down_sync(0xffffffffu, sc, off);
    }
    if (lane == 0) {
        g_hpk[b * HH + u] = pk_split(sh + bh[u]);
        g_c0[b * HH + u]  = sc + bc[u];
    }
}

// ---------------------------------------------------------------------------
// Persistent HMMA recurrence. 128 CTAs x 8 warps. W slice resident in SMEM.
// Fine-grained producer flags (per step x 64-column group) instead of a global
// barrier; chunk order rotated per CTA (start at own group) to balance L2.
// SMEM: [0..128) b0s, [128..256) bFs | 1024: W_hi (64K), 66560: W_lo (64K)
//       A bufs: 132096/148480 (buf0 hi/lo), 164864/181248 (buf1 hi/lo)
// ---------------------------------------------------------------------------
#define S_WHI 1024
#define S_WLO 66560
#define A0H 132096
#define A0L 148480
#define A1H 164864
#define A1L 181248
#define S_TOT 197632

__global__ void __launch_bounds__(NTHR, 1) k_steps_mma() {
    extern __shared__ unsigned char sm[];
    const unsigned sb = smem_u32(sm);
    const int tid = threadIdx.x, blk = blockIdx.x;
    const int w = tid >> 5, lane = tid & 31;
    const int q = lane & 3, gr = lane >> 2, ls = lane >> 3;
    const int myg = blk >> 3;
    float* b0s = (float*)(sm);
    float* bFs = (float*)(sm + 128);

    if (tid < 32) {
        b0s[tid] = g_b0[blk * 32 + tid];
        bFs[tid] = g_bF[blk * 32 + tid];
    }
    {   // W slices for step 0 (W_hh only)
        const uint4* src = (const uint4*)(g_Wsw0 + (size_t)blk * 131072);
        uint4* dst = (uint4*)(sm + S_WHI);
        for (int i = tid; i < 8192; i += NTHR) dst[i] = src[i];
    }
    // cell state in registers: thread owns (m, m+8) x (2q, 2q+1)
    float cst[2][2];
    {
        int m0 = (w << 4) + gr;
        float2 v0 = *(const float2*)(g_c0 + m0 * HH + (blk << 3) + (q << 1));
        float2 v1 = *(const float2*)(g_c0 + (m0 + 8) * HH + (blk << 3) + (q << 1));
        cst[0][0] = v0.x; cst[0][1] = v0.y;
        cst[1][0] = v1.x; cst[1][1] = v1.y;
    }
    __syncthreads();

    // per-thread ldmatrix base offsets
    const unsigned aBase = (unsigned)(((w * 2 + (ls & 1)) * 8 + (ls >> 1)) * 128 + (lane & 7) * 16);
    const unsigned bBase = (unsigned)((((ls >> 1) * 2 + (ls & 1)) * 128) + (lane & 7) * 16);
    // staging mapping: row = p*16 + (tid&15), c0 = (tid>>4)*4
    const int srow = tid & 15;
    const int kc4  = tid >> 4;            // c0>>2
    const int c0   = kc4 << 2;
    const int sOff = ((srow >> 3) * 8 + (c0 >> 3)) * 128 + (srow & 7) * 16 + ((c0 & 7) << 1);

    for (int t = 0; t < TT; ++t) {
        const uint4* hp4 = (const uint4*)(g_hpk + (size_t)t * BH);
        float acc[4][4];
        #pragma unroll
        for (int a = 0; a < 4; ++a)
            #pragma unroll
            for (int b = 0; b < 4; ++b) acc[a][b] = 0.f;

        uint4 pre[8];
        if (t) waitflag(t, myg);
        #pragma unroll
        for (int p = 0; p < 8; ++p)
            pre[p] = __ldcg(hp4 + p * 4096 + srow * 256 + myg * 16 + kc4);
        // stage first chunk -> buf0
        #pragma unroll
        for (int p = 0; p < 8; ++p) {
            uint4 v = pre[p];
            unsigned h0 = __byte_perm(v.x, v.y, 0x5410), l0 = __byte_perm(v.x, v.y, 0x7632);
            unsigned h1 = __byte_perm(v.z, v.w, 0x5410), l1 = __byte_perm(v.z, v.w, 0x7632);
            int off = p * 2048 + sOff;
            *(uint2*)(sm + A0H + off) = make_uint2(h0, h1);
            *(uint2*)(sm + A0L + off) = make_uint2(l0, l1);
        }
        __syncthreads();

        for (int i = 0; i < 16; ++i) {
            int buf = i & 1;
            int ck  = (myg + i) & 15;       // absolute chunk this iteration computes
            int nck = (myg + i + 1) & 15;   // next chunk to prefetch
            if (i < 15) {
                if (t) waitflag(t, nck);
                #pragma unroll
                for (int p = 0; p < 8; ++p)
                    pre[p] = __ldcg(hp4 + p * 4096 + srow * 256 + nck * 16 + kc4);
            }
            unsigned Abh = sb + (buf ? A1H : A0H);
            unsigned Abl = sb + (buf ? A1L : A0L);
            #pragma unroll
            for (int kk = 0; kk < 4; ++kk) {
                unsigned Ah[4], Al[4];
                ldsm4(Ah, Abh + aBase + kk * 256);
                ldsm4(Al, Abl + aBase + kk * 256);
                int ckk = ck * 4 + kk;
                #pragma unroll
                for (int gg = 0; gg < 2; ++gg) {
                    unsigned Bh[4], Bl[4];
                    ldsm4(Bh, sb + S_WHI + ckk * 1024 + gg * 512 + bBase);
                    ldsm4(Bl, sb + S_WLO + ckk * 1024 + gg * 512 + bBase);
                    mma16816(acc[2 * gg],     Ah, Bh);
                    mma16816(acc[2 * gg],     Ah, Bl);
                    mma16816(acc[2 * gg],     Al, Bh);
                    mma16816(acc[2 * gg + 1], Ah, Bh + 2);
                    mma16816(acc[2 * gg + 1], Ah, Bl + 2);
                    mma16816(acc[2 * gg + 1], Al, Bh + 2);
                }
            }
            if (i < 15) {   // stage prefetched chunk -> other buf
                unsigned hb = buf ? A0H : A1H, lb = buf ? A0L : A1L;
                #pragma unroll
                for (int p = 0; p < 8; ++p) {
                    uint4 v = pre[p];
                    unsigned h0 = __byte_perm(v.x, v.y, 0x5410), l0 = __byte_perm(v.x, v.y, 0x7632);
                    unsigned h1 = __byte_perm(v.z, v.w, 0x5410), l1 = __byte_perm(v.z, v.w, 0x7632);
                    int off = p * 2048 + sOff;
                    *(uint2*)(sm + hb + off) = make_uint2(h0, h1);
                    *(uint2*)(sm + lb + off) = make_uint2(l0, l1);
                }
            }
            __syncthreads();
        }

        // epilogue: 4 gates of (m, u) live in this thread — no shuffles
        const float* bs = t ? bFs : b0s;
        unsigned* hn = g_hpk + (size_t)(t + 1) * BH;
        #pragma unroll
        for (int r = 0; r < 2; ++r) {
            int m = (w << 4) + gr + (r << 3);
            unsigned pk2[2];
            #pragma unroll
            for (int s = 0; s < 2; ++s) {
                int u = (q << 1) + s;
                int fi = r * 2 + s;
                float ig = acc[0][fi] + bs[u];
                float fg = acc[1][fi] + bs[8 + u];
                float gg = acc[2][fi] + bs[16 + u];
                float og = acc[3][fi] + bs[24 + u];
                float cn = sigf(fg) * cst[r][s] + sigf(ig) * tanhf(gg);
                cst[r][s] = cn;
                pk2[s] = pk_split(sigf(og) * tanhf(cn));
            }
            *(uint2*)(hn + m * HH + (blk << 3) + (q << 1)) = make_uint2(pk2[0], pk2[1]);
        }

        // release: EVERY thread fences its own h stores to GPU scope, then
        // barrier, then tid0 posts with a release atomic. (tid0-only fence was
        // the R9 race: it only ordered tid0's stores.)
        __threadfence();
        __syncthreads();
        if (tid == 0) postflag(t + 1, myg);

        if (t == 0) {   // swap in folded weights for steps >= 1
            const uint4* src = (const uint4*)(g_WswF + (size_t)blk * 131072);
            uint4* dst = (uint4*)(sm + S_WHI);
            for (int i = tid; i < 8192; i += NTHR) dst[i] = src[i];
            __syncthreads();
        }
    }
}

// ---------------------------------------------------------------------------
// Output GEMM: out[b,t,o] = leaky(hs . W_out^T + b_out). M=32768,N=1024,K=1024.
// 128x64 tiles, HMMA 3-split. grid(16 nb, 256 mb), 256 thr, occupancy 2.
// SMEM: bias 0..256 | A: 1024/17408 (b0 hi/lo), 33792/50176 (b1) | B: 66560/82944
// ---------------------------------------------------------------------------
#define OB_A0H 1024
#define OB_A0L 17408
#define OB_A1H 33792
#define OB_A1L 50176
#define OB_B0  66560
#define OB_B1  82944
#define SO_TOT 99328

__global__ void __launch_bounds__(256, 2) k_out_mma(const float* __restrict__ bout,
                                                    float* __restrict__ out) {
    extern __shared__ unsigned char sm[];
    const unsigned sb = smem_u32(sm);
    const int tid = threadIdx.x;
    const int w = tid >> 5, lane = tid & 31;
    const int q = lane & 3, gr = lane >> 2, ls = lane >> 3;
    const int nb = blockIdx.x, mb = blockIdx.y;
    float* bias_s = (float*)(sm);
    if (tid < 64) bias_s[tid] = bout[nb * 64 + tid];
    __syncthreads();

    const unsigned aBase = (unsigned)(((w * 2 + (ls & 1)) * 8 + (ls >> 1)) * 128 + (lane & 7) * 16);
    const unsigned bBase = (unsigned)((((ls >> 1) * 2 + (ls & 1)) * 128) + (lane & 7) * 16);
    const int srow = tid & 15;
    const int kc4  = tid >> 4;
    const int c0   = kc4 << 2;
    const int sOff = ((srow >> 3) * 8 + (c0 >> 3)) * 128 + (srow & 7) * 16 + ((c0 & 7) << 1);

    const uint4* A4 = (const uint4*)(g_hpk + BH) + (size_t)(mb * 128) * 256;
    const uint4* B4 = (const uint4*)g_WoT + (size_t)nb * 16384;

    float acc[8][4];
    #pragma unroll
    for (int a = 0; a < 8; ++a)
        #pragma unroll
        for (int b = 0; b < 4; ++b) acc[a][b] = 0.f;

    uint4 preA[8], preB[4];
    #pragma unroll
    for (int p = 0; p < 8; ++p) preA[p] = __ldcg(A4 + p * 4096 + srow * 256 + kc4);
    #pragma unroll
    for (int j = 0; j < 4; ++j) preB[j] = __ldcg(B4 + tid + j * 256);
    // stage chunk 0 -> buf0
    #pragma unroll
    for (int p = 0; p < 8; ++p) {
        uint4 v = preA[p];
        unsigned h0 = __byte_perm(v.x, v.y, 0x5410), l0 = __byte_perm(v.x, v.y, 0x7632);
        unsigned h1 = __byte_perm(v.z, v.w, 0x5410), l1 = __byte_perm(v.z, v.w, 0x7632);
        int off = p * 2048 + sOff;
        *(uint2*)(sm + OB_A0H + off) = make_uint2(h0, h1);
        *(uint2*)(sm + OB_A0L + off) = make_uint2(l0, l1);
    }
    #pragma unroll
    for (int j = 0; j < 4; ++j) ((uint4*)(sm + OB_B0))[tid + j * 256] = preB[j];
    __syncthreads();

    for (int ch = 0; ch < 16; ++ch) {
        int buf = ch & 1;
        if (ch < 15) {
            #pragma unroll
            for (int p = 0; p < 8; ++p)
                preA[p] = __ldcg(A4 + p * 4096 + srow * 256 + (ch + 1) * 16 + kc4);
            #pragma unroll
            for (int j = 0; j < 4; ++j)
                preB[j] = __ldcg(B4 + (ch + 1) * 1024 + tid + j * 256);
        }
        unsigned Abh  = sb + (buf ? OB_A1H : OB_A0H);
        unsigned Abl  = sb + (buf ? OB_A1L : OB_A0L);
        unsigned Bsel = sb + (buf ? OB_B1  : OB_B0);
        #pragma unroll
        for (int kk = 0; kk < 4; ++kk) {
            unsigned Ah[4], Al[4];
            ldsm4(Ah, Abh + aBase + kk * 256);
            ldsm4(Al, Abl + aBase + kk * 256);
            #pragma unroll
            for (int gg = 0; gg < 4; ++gg) {
                unsigned Bh[4], Bl[4];
                ldsm4(Bh, Bsel + kk * 2048 + gg * 512 + bBase);          // split 0 (hi)
                ldsm4(Bl, Bsel + 8192 + kk * 2048 + gg * 512 + bBase);   // split 1 (lo)
                mma16816(acc[2 * gg],     Ah, Bh);
                mma16816(acc[2 * gg],     Ah, Bl);
                mma16816(acc[2 * gg],     Al, Bh);
                mma16816(acc[2 * gg + 1], Ah, Bh + 2);
                mma16816(acc[2 * gg + 1], Ah, Bl + 2);
                mma16816(acc[2 * gg + 1], Al, Bh + 2);
            }
        }
        if (ch < 15) {
            unsigned hb = buf ? OB_A0H : OB_A1H, lb = buf ? OB_A0L : OB_A1L;
            unsigned bb = buf ? OB_B0 : OB_B1;
            #pragma unroll
            for (int p = 0; p < 8; ++p) {
                uint4 v = preA[p];
                unsigned h0 = __byte_perm(v.x, v.y, 0x5410), l0 = __byte_perm(v.x, v.y, 0x7632);
                unsigned h1 = __byte_perm(v.z, v.w, 0x5410), l1 = __byte_perm(v.z, v.w, 0x7632);
                int off = p * 2048 + sOff;
                *(uint2*)(sm + hb + off) = make_uint2(h0, h1);
                *(uint2*)(sm + lb + off) = make_uint2(l0, l1);
            }
            #pragma unroll
            for (int j = 0; j < 4; ++j) ((uint4*)(sm + bb))[tid + j * 256] = preB[j];
        }
        __syncthreads();
    }

    // epilogue: bias + LeakyReLU, float2 stores
    #pragma unroll
    for (int nt = 0; nt < 8; ++nt) {
        int o0 = nb * 64 + nt * 8 + (q << 1);
        float bo0 = bias_s[nt * 8 + (q << 1)];
        float bo1 = bias_s[nt * 8 + (q << 1) + 1];
        #pragma unroll
        for (int r = 0; r < 2; ++r) {
            int m = mb * 128 + (w << 4) + gr + (r << 3);
            int tt = m >> 7, b = m & 127;
            float x0 = acc[nt][r * 2]     + bo0;
            float x1 = acc[nt][r * 2 + 1] + bo1;
            float2 v;
            v.x = x0 >= 0.f ? x0 : 0.2f * x0;
            v.y = x1 >= 0.f ? x1 : 0.2f * x1;
            *(float2*)(out + (size_t)b * (TT * OO) + (size_t)tt * OO + o0) = v;
        }
    }
}

// ---------------------------------------------------------------------------
extern "C" void kernel_launch(void* const* d_in, const int* in_sizes, int n_in,
                              void* d_out, int out_size) {
    const float* z      = (const float*)d_in[0];
    const float* W_fc_h = (const float*)d_in[2];
    const float* b_fc_h = (const float*)d_in[3];
    const float* W_fc_c = (const float*)d_in[4];
    const float* b_fc_c = (const float*)d_in[5];
    const float* W_ih   = (const float*)d_in[6];
    const float* b_ih   = (const float*)d_in[7];
    const float* W_hh   = (const float*)d_in[8];
    const float* b_hh   = (const float*)d_in[9];
    const float* x0     = (const float*)d_in[10];
    const float* W_out  = (const float*)d_in[11];
    const float* b_out  = (const float*)d_in[12];
    float* out = (float*)d_out;

    k_zero<<<17, 256>>>();
    k_foldw<<<16384, 256>>>(W_ih, W_hh);
    k_foldo<<<4096, 256>>>(W_out);
    k_bias<<<512, 256>>>(W_ih, b_ih, b_hh, x0);
    k_init<<<16384, 256>>>(z, W_fc_h, b_fc_h, W_fc_c, b_fc_c);

    cudaFuncSetAttribute(k_steps_mma, cudaFuncAttributeMaxDynamicSharedMemorySize, S_TOT);
    k_steps_mma<<<NBLK, NTHR, S_TOT>>>();

    cudaFuncSetAttribute(k_out_mma, cudaFuncAttributeMaxDynamicSharedMemorySize, SO_TOT);
    k_out_mma<<<dim3(16, 256), 256, SO_TOT>>>(b_out, out);
}

// round 11
// speedup vs baseline: 2.6835x; 2.6835x over previous
#include <cuda_runtime.h>
#include <cuda_bf16.h>

#define Bb   128
#define DIN  512
#define HH   1024
#define G4   4096
#define TT   256
#define OO   1024
#define BH   (Bb*HH)
#define NBLK 128
#define NTHR 256
#define SLOT 524288   // per-step h slot: 16 chunks x (16KB hi + 16KB lo)

// ---- device-global scratch ----
__device__ __align__(16) unsigned char g_hT[(TT+1)*SLOT];    // h history, tiled + split
__device__ __align__(16) float         g_c0[BH];             // initial cell state
__device__ __align__(16) unsigned char g_WswF[NBLK*131072];  // folded slices (t>=1)
__device__ __align__(16) unsigned char g_Wsw0[NBLK*131072];  // W_hh slices (t==0)
__device__ __align__(16) unsigned char g_WoT[16*16*16384];   // W_out tiles
__device__ float    g_bF[G4];
__device__ float    g_b0[G4];
__device__ unsigned g_bar[TT];                               // monotonic barrier counters

__device__ __forceinline__ float sigf(float x) { return 1.0f / (1.0f + __expf(-x)); }

__device__ __forceinline__ unsigned smem_u32(const void* p) {
    return (unsigned)__cvta_generic_to_shared(p);
}
__device__ __forceinline__ void ldsm4(unsigned* r, unsigned addr) {
    asm volatile("ldmatrix.sync.aligned.m8n8.x4.shared.b16 {%0,%1,%2,%3}, [%4];"
                 : "=r"(r[0]), "=r"(r[1]), "=r"(r[2]), "=r"(r[3]) : "r"(addr));
}
__device__ __forceinline__ void mma16816(float* d, const unsigned* a, const unsigned* b) {
    asm volatile("mma.sync.aligned.m16n8k16.row.col.f32.bf16.bf16.f32 "
                 "{%0,%1,%2,%3}, {%4,%5,%6,%7}, {%8,%9}, {%0,%1,%2,%3};"
                 : "+f"(d[0]), "+f"(d[1]), "+f"(d[2]), "+f"(d[3])
                 : "r"(a[0]), "r"(a[1]), "r"(a[2]), "r"(a[3]), "r"(b[0]), "r"(b[1]));
}
__device__ __forceinline__ void cpasync16(unsigned saddr, const void* g) {
    asm volatile("cp.async.cg.shared.global [%0], [%1], 16;" :: "r"(saddr), "l"(g));
}
__device__ __forceinline__ void cpcommit() { asm volatile("cp.async.commit_group;" ::: "memory"); }
template<int N> __device__ __forceinline__ void cpwait() {
    asm volatile("cp.async.wait_group %0;" :: "n"(N) : "memory");
}

// pack two floats as (bf16(a) | bf16(b)<<16) for hi plane, and residuals for lo
__device__ __forceinline__ void split2(float a, float b, unsigned& hipk, unsigned& lopk) {
    __nv_bfloat16 ha = __float2bfloat16(a);
    __nv_bfloat16 hb = __float2bfloat16(b);
    __nv_bfloat16 la = __float2bfloat16(a - __bfloat162float(ha));
    __nv_bfloat16 lb = __float2bfloat16(b - __bfloat162float(hb));
    hipk = (unsigned)__bfloat16_as_ushort(ha) | ((unsigned)__bfloat16_as_ushort(hb) << 16);
    lopk = (unsigned)__bfloat16_as_ushort(la) | ((unsigned)__bfloat16_as_ushort(lb) << 16);
}

// ---------------------------------------------------------------------------
// k_foldw: permute + fold weights into per-block slice tiles (ldmatrix-native).
// ---------------------------------------------------------------------------
__global__ void k_foldw(const float* __restrict__ Wih, const float* __restrict__ Whh) {
    int i = blockIdx.x * blockDim.x + threadIdx.x;   // 4,194,304
    int k = i & 1023, rr = (i >> 10) & 31, blk = i >> 15;
    int gate = rr >> 3, unit = rr & 7;
    int j = (gate << 10) + (blk << 3) + unit;
    float a = Wih[(size_t)j * HH + k];
    float b = Whh[(size_t)j * HH + k];
    float f = a + b;
    int off = ((k >> 4) << 10) + (((gate << 1) + ((k >> 3) & 1)) << 7) + (unit << 4) + ((k & 7) << 1);
    unsigned char* bF = g_WswF + (size_t)blk * 131072;
    unsigned char* b0 = g_Wsw0 + (size_t)blk * 131072;
    __nv_bfloat16 fh = __float2bfloat16(f);
    __nv_bfloat16 fl = __float2bfloat16(f - __bfloat162float(fh));
    *(__nv_bfloat16*)(bF + off)         = fh;
    *(__nv_bfloat16*)(bF + 65536 + off) = fl;
    __nv_bfloat16 wh = __float2bfloat16(b);
    __nv_bfloat16 wl = __float2bfloat16(b - __bfloat162float(wh));
    *(__nv_bfloat16*)(b0 + off)         = wh;
    *(__nv_bfloat16*)(b0 + 65536 + off) = wl;
}

// W_out -> [nb(16)][ch(16)] 16KB blocks: hi 8KB [ck4][nt*2+kt][16x128B] then lo 8KB
__global__ void k_foldo(const float* __restrict__ Wout) {
    int i = blockIdx.x * blockDim.x + threadIdx.x;   // 1,048,576
    int k = i & 1023, o = i >> 10;
    int nb = o >> 6, nt = (o >> 3) & 7, r = o & 7;
    int ch = k >> 6, ck4 = (k >> 4) & 3, kt = (k >> 3) & 1, c = k & 7;
    unsigned char* base = g_WoT + (size_t)(nb * 16 + ch) * 16384;
    int toff = (ck4 << 11) + (((nt << 1) + kt) << 7) + (r << 4) + (c << 1);
    float w = Wout[(size_t)o * HH + k];
    __nv_bfloat16 hi = __float2bfloat16(w);
    __nv_bfloat16 lo = __float2bfloat16(w - __bfloat162float(hi));
    *(__nv_bfloat16*)(base + toff)        = hi;
    *(__nv_bfloat16*)(base + 8192 + toff) = lo;
}

// bias fold (perm order r = gate*8+unit per blk)
__global__ void k_bias(const float* __restrict__ Wih, const float* __restrict__ bih,
                       const float* __restrict__ bhh, const float* __restrict__ x0) {
    int w    = (blockIdx.x * blockDim.x + threadIdx.x) >> 5;
    int lane = threadIdx.x & 31;
    if (w >= G4) return;
    int blk = w >> 5, lr = w & 31;
    int j   = (blk << 3) + (lr & 7) + ((lr >> 3) << 10);
    float s = 0.f;
    for (int k = lane; k < HH; k += 32) s += x0[k] * Wih[(size_t)j * HH + k];
    #pragma unroll
    for (int off = 16; off; off >>= 1) s += __shfl_down_sync(0xffffffffu, s, off);
    if (lane == 0) {
        float bf = bih[j] + bhh[j];
        g_bF[w] = bf;
        g_b0[w] = bf + s;
    }
}

// h0 (split, tiled) -> g_hT slot 0 ; c0 -> g_c0
__global__ void k_init(const float* __restrict__ z,
                       const float* __restrict__ Wh, const float* __restrict__ bh,
                       const float* __restrict__ Wc, const float* __restrict__ bc) {
    int w    = (blockIdx.x * blockDim.x + threadIdx.x) >> 5;
    int lane = threadIdx.x & 31;
    int b = w >> 10, u = w & 1023;
    float sh = 0.f, sc = 0.f;
    for (int k = lane; k < DIN; k += 32) {
        float zv = z[b * DIN + k];
        sh += zv * Wh[u * DIN + k];
        sc += zv * Wc[u * DIN + k];
    }
    #pragma unroll
    for (int off = 16; off; off >>= 1) {
        sh += __shfl_down_sync(0xffffffffu, sh, off);
        sc += __shfl_down_sync(0xffffffffu, sc, off);
    }
    if (lane == 0) {
        float hv = sh + bh[u];
        __nv_bfloat16 hhi = __float2bfloat16(hv);
        __nv_bfloat16 hlo = __float2bfloat16(hv - __bfloat162float(hhi));
        int ck = u >> 6, c = u & 63;
        int toff = (((b >> 3) << 3) + (c >> 3)) * 128 + ((b & 7) << 4) + ((c & 7) << 1);
        unsigned char* dst = g_hT + (size_t)ck * 32768 + toff;
        *(__nv_bfloat16*)dst             = hhi;
        *(__nv_bfloat16*)(dst + 16384)   = hlo;
        g_c0[b * HH + u] = sc + bc[u];
    }
}

// ---------------------------------------------------------------------------
// Persistent HMMA recurrence. 128 CTAs x 8 warps. W slice resident in SMEM.
// h staged via cp.async (pre-split, pre-tiled in gmem), 3-deep ring.
// SMEM: [0..128) b0s [128..256) bFs | 1024 W_hi 64K | 66560 W_lo 64K |
//       A ring: 132096 / 164864 / 197632 (32KB each: hi 16K + lo 16K)
// ---------------------------------------------------------------------------
#define S_WHI 1024
#define S_WLO 66560
#define S_TOT 230400

__global__ void __launch_bounds__(NTHR, 1) k_steps_mma() {
    extern __shared__ unsigned char sm[];
    const unsigned sb = smem_u32(sm);
    const int tid = threadIdx.x, blk = blockIdx.x;
    const int w = tid >> 5, lane = tid & 31;
    const int q = lane & 3, gr = lane >> 2, ls = lane >> 3;
    float* b0s = (float*)(sm);
    float* bFs = (float*)(sm + 128);

    if (tid < 32) {
        b0s[tid] = g_b0[blk * 32 + tid];
        bFs[tid] = g_bF[blk * 32 + tid];
    }
    {   // W slices for step 0 (W_hh only)
        const uint4* src = (const uint4*)(g_Wsw0 + (size_t)blk * 131072);
        uint4* dst = (uint4*)(sm + S_WHI);
        for (int i = tid; i < 8192; i += NTHR) dst[i] = src[i];
    }
    float cst[2][2];
    {
        int m0 = (w << 4) + gr;
        float2 v0 = *(const float2*)(g_c0 + m0 * HH + (blk << 3) + (q << 1));
        float2 v1 = *(const float2*)(g_c0 + (m0 + 8) * HH + (blk << 3) + (q << 1));
        cst[0][0] = v0.x; cst[0][1] = v0.y;
        cst[1][0] = v1.x; cst[1][1] = v1.y;
    }
    __syncthreads();

    const unsigned aBase = (unsigned)(((w * 2 + (ls & 1)) * 8 + (ls >> 1)) * 128 + (lane & 7) * 16);
    const unsigned bBase = (unsigned)((((ls >> 1) * 2 + (ls & 1)) * 128) + (lane & 7) * 16);
    const int cpo = tid * 16;

    for (int t = 0; t < TT; ++t) {
        const unsigned char* hsrc = g_hT + (size_t)t * SLOT;
        unsigned cur = sb + 132096u, nxt = sb + 164864u, fre = sb + 197632u;

        // prologue: chunk 0 -> cur, chunk 1 -> nxt
        #pragma unroll
        for (int j = 0; j < 8; ++j) cpasync16(cur + cpo + j * 4096, hsrc + cpo + j * 4096);
        cpcommit();
        #pragma unroll
        for (int j = 0; j < 8; ++j) cpasync16(nxt + cpo + j * 4096, hsrc + 32768 + cpo + j * 4096);
        cpcommit();

        float acc[4][4];
        #pragma unroll
        for (int a = 0; a < 4; ++a)
            #pragma unroll
            for (int b = 0; b < 4; ++b) acc[a][b] = 0.f;

        for (int i = 0; i < 16; ++i) {
            if (i < 15) cpwait<1>(); else cpwait<0>();
            __syncthreads();
            if (i < 14) {   // prefetch chunk i+2 into the buffer freed by chunk i-1
                const unsigned char* src = hsrc + (size_t)(i + 2) * 32768;
                #pragma unroll
                for (int j = 0; j < 8; ++j) cpasync16(fre + cpo + j * 4096, src + cpo + j * 4096);
                cpcommit();
            }
            #pragma unroll
            for (int kk = 0; kk < 4; ++kk) {
                unsigned Ah[4], Al[4];
                ldsm4(Ah, cur + aBase + kk * 256);
                ldsm4(Al, cur + 16384 + aBase + kk * 256);
                int ckk = i * 4 + kk;
                #pragma unroll
                for (int gg = 0; gg < 2; ++gg) {
                    unsigned Bh[4], Bl[4];
                    ldsm4(Bh, sb + S_WHI + ckk * 1024 + gg * 512 + bBase);
                    ldsm4(Bl, sb + S_WLO + ckk * 1024 + gg * 512 + bBase);
                    mma16816(acc[2 * gg],     Ah, Bh);
                    mma16816(acc[2 * gg],     Ah, Bl);
                    mma16816(acc[2 * gg],     Al, Bh);
                    mma16816(acc[2 * gg + 1], Ah, Bh + 2);
                    mma16816(acc[2 * gg + 1], Ah, Bl + 2);
                    mma16816(acc[2 * gg + 1], Al, Bh + 2);
                }
            }
            unsigned tmp = cur; cur = nxt; nxt = fre; fre = tmp;
        }

        // epilogue: 4 gates of (b, u) live in this thread — write h in tiled/split form
        const float* bs = t ? bFs : b0s;
        unsigned char* hd = g_hT + (size_t)(t + 1) * SLOT + (size_t)(blk >> 3) * 32768;
        const int cb = blk & 7;
        #pragma unroll
        for (int r = 0; r < 2; ++r) {
            float hv[2];
            #pragma unroll
            for (int s = 0; s < 2; ++s) {
                int u = (q << 1) + s;
                int fi = r * 2 + s;
                float ig = acc[0][fi] + bs[u];
                float fg = acc[1][fi] + bs[8 + u];
                float gg = acc[2][fi] + bs[16 + u];
                float og = acc[3][fi] + bs[24 + u];
                float cn = sigf(fg) * cst[r][s] + sigf(ig) * tanhf(gg);
                cst[r][s] = cn;
                hv[s] = sigf(og) * tanhf(cn);
            }
            unsigned hipk, lopk;
            split2(hv[0], hv[1], hipk, lopk);
            int toff = (((2 * w + r) << 3) + cb) * 128 + (gr << 4) + (q << 2);
            *(unsigned*)(hd + toff)         = hipk;
            *(unsigned*)(hd + 16384 + toff) = lopk;
        }

        // global barrier (monotonic, replay-safe; all-thread fence -> release post)
        __threadfence();
        __syncthreads();
        if (tid == 0) {
            unsigned old;
            asm volatile("atom.release.gpu.global.add.u32 %0, [%1], %2;"
                         : "=r"(old) : "l"(&g_bar[t]), "r"(1u) : "memory");
            unsigned target = old - (old & (NBLK - 1)) + NBLK;
            unsigned v;
            do {
                asm volatile("ld.acquire.gpu.global.u32 %0, [%1];"
                             : "=r"(v) : "l"(&g_bar[t]) : "memory");
            } while ((int)(v - target) < 0);
        }
        __syncthreads();

        if (t == 0) {   // swap in folded weights for steps >= 1
            const uint4* src = (const uint4*)(g_WswF + (size_t)blk * 131072);
            uint4* dst = (uint4*)(sm + S_WHI);
            for (int i2 = tid; i2 < 8192; i2 += NTHR) dst[i2] = src[i2];
            // visibility guaranteed by the __syncthreads at iteration 0 of t=1
        }
    }
}

// ---------------------------------------------------------------------------
// Output GEMM via cp.async staging. A from g_hT (tile layout matches), B from
// g_WoT. 128x64 tiles, 2-deep ring (48KB/buf), occupancy 2.
// SMEM: bias 0..256 | buf0 1024 | buf1 50176  (A hi +0, A lo +16384, B +32768)
// ---------------------------------------------------------------------------
#define KO_B0 1024
#define KO_B1 50176
#define SO_TOT 99328

__global__ void __launch_bounds__(256, 2) k_out_mma(const float* __restrict__ bout,
                                                    float* __restrict__ out) {
    extern __shared__ unsigned char sm[];
    const unsigned sb = smem_u32(sm);
    const int tid = threadIdx.x;
    const int w = tid >> 5, lane = tid & 31;
    const int q = lane & 3, gr = lane >> 2, ls = lane >> 3;
    const int nb = blockIdx.x, mb = blockIdx.y;
    float* bias_s = (float*)(sm);
    if (tid < 64) bias_s[tid] = bout[nb * 64 + tid];

    const unsigned aBase = (unsigned)(((w * 2 + (ls & 1)) * 8 + (ls >> 1)) * 128 + (lane & 7) * 16);
    const unsigned bBase = (unsigned)((((ls >> 1) * 2 + (ls & 1)) * 128) + (lane & 7) * 16);
    const int cpo = tid * 16;
    const unsigned char* Asrc = g_hT + (size_t)(mb + 1) * SLOT;
    const unsigned char* Bsrc = g_WoT + (size_t)nb * 16 * 16384;

    auto issue = [&](int ch, unsigned buf) {
        const unsigned char* a = Asrc + (size_t)ch * 32768;
        #pragma unroll
        for (int j = 0; j < 8; ++j) cpasync16(buf + cpo + j * 4096, a + cpo + j * 4096);
        const unsigned char* bsc = Bsrc + (size_t)ch * 16384;
        #pragma unroll
        for (int j = 0; j < 4; ++j) cpasync16(buf + 32768 + cpo + j * 4096, bsc + cpo + j * 4096);
        cpcommit();
    };

    unsigned cur = sb + KO_B0, oth = sb + KO_B1;
    issue(0, cur);
    issue(1, oth);

    float acc[8][4];
    #pragma unroll
    for (int a = 0; a < 8; ++a)
        #pragma unroll
        for (int b = 0; b < 4; ++b) acc[a][b] = 0.f;

    for (int i = 0; i < 16; ++i) {
        if (i < 15) cpwait<1>(); else cpwait<0>();
        __syncthreads();
        #pragma unroll
        for (int kk = 0; kk < 4; ++kk) {
            unsigned Ah[4], Al[4];
            ldsm4(Ah, cur + aBase + kk * 256);
            ldsm4(Al, cur + 16384 + aBase + kk * 256);
            #pragma unroll
            for (int gg = 0; gg < 4; ++gg) {
                unsigned Bh[4], Bl[4];
                ldsm4(Bh, cur + 32768 + kk * 2048 + gg * 512 + bBase);
                ldsm4(Bl, cur + 40960 + kk * 2048 + gg * 512 + bBase);
                mma16816(acc[2 * gg],     Ah, Bh);
                mma16816(acc[2 * gg],     Ah, Bl);
                mma16816(acc[2 * gg],     Al, Bh);
                mma16816(acc[2 * gg + 1], Ah, Bh + 2);
                mma16816(acc[2 * gg + 1], Ah, Bl + 2);
                mma16816(acc[2 * gg + 1], Al, Bh + 2);
            }
        }
        __syncthreads();
        if (i < 14) issue(i + 2, cur);
        unsigned tmp = cur; cur = oth; oth = tmp;
    }

    // epilogue: bias + LeakyReLU, float2 stores
    #pragma unroll
    for (int nt = 0; nt < 8; ++nt) {
        int o0 = nb * 64 + nt * 8 + (q << 1);
        float bo0 = bias_s[nt * 8 + (q << 1)];
        float bo1 = bias_s[nt * 8 + (q << 1) + 1];
        #pragma unroll
        for (int r = 0; r < 2; ++r) {
            int m = mb * 128 + (w << 4) + gr + (r << 3);
            int tt = m >> 7, b = m & 127;
            float x0 = acc[nt][r * 2]     + bo0;
            float x1 = acc[nt][r * 2 + 1] + bo1;
            float2 v;
            v.x = x0 >= 0.f ? x0 : 0.2f * x0;
            v.y = x1 >= 0.f ? x1 : 0.2f * x1;
            *(float2*)(out + (size_t)b * (TT * OO) + (size_t)tt * OO + o0) = v;
        }
    }
}

// ---------------------------------------------------------------------------
extern "C" void kernel_launch(void* const* d_in, const int* in_sizes, int n_in,
                              void* d_out, int out_size) {
    const float* z      = (const float*)d_in[0];
    const float* W_fc_h = (const float*)d_in[2];
    const float* b_fc_h = (const float*)d_in[3];
    const float* W_fc_c = (const float*)d_in[4];
    const float* b_fc_c = (const float*)d_in[5];
    const float* W_ih   = (const float*)d_in[6];
    const float* b_ih   = (const float*)d_in[7];
    const float* W_hh   = (const float*)d_in[8];
    const float* b_hh   = (const float*)d_in[9];
    const float* x0     = (const float*)d_in[10];
    const float* W_out  = (const float*)d_in[11];
    const float* b_out  = (const float*)d_in[12];
    float* out = (float*)d_out;

    k_foldw<<<16384, 256>>>(W_ih, W_hh);
    k_foldo<<<4096, 256>>>(W_out);
    k_bias<<<512, 256>>>(W_ih, b_ih, b_hh, x0);
    k_init<<<16384, 256>>>(z, W_fc_h, b_fc_h, W_fc_c, b_fc_c);

    cudaFuncSetAttribute(k_steps_mma, cudaFuncAttributeMaxDynamicSharedMemorySize, S_TOT);
    k_steps_mma<<<NBLK, NTHR, S_TOT>>>();

    cudaFuncSetAttribute(k_out_mma, cudaFuncAttributeMaxDynamicSharedMemorySize, SO_TOT);
    k_out_mma<<<dim3(16, 256), 256, SO_TOT>>>(b_out, out);
}

// round 12
// speedup vs baseline: 3.8634x; 1.4397x over previous
#include <cuda_runtime.h>
#include <cuda_fp16.h>

#define Bb   128
#define DIN  512
#define HH   1024
#define G4   4096
#define TT   256
#define OO   1024
#define BH   (Bb*HH)
#define NBLK 128
#define NTHR 256
#define SLOT 262144   // per-step h slot: 16 chunks x 16KB (fp16 single plane)
#define INVS 0.000244140625f   // 1/4096

// ---- device-global scratch ----
__device__ __align__(16) unsigned char g_hT[(TT+1)*SLOT];    // h history, tiled fp16
__device__ __align__(16) float         g_c0[BH];             // initial cell state
__device__ __align__(16) unsigned char g_WswF[NBLK*131072];  // folded slices: fp16 hi + lo*4096
__device__ __align__(16) unsigned char g_Wsw0[NBLK*131072];  // W_hh slices (t==0), same format
__device__ __align__(16) unsigned char g_WoT[16*16*16384];   // W_out tiles: hi 8KB + lo*4096 8KB
__device__ float    g_bF[G4];
__device__ float    g_b0[G4];
__device__ unsigned g_bar[TT];                               // monotonic barrier counters

__device__ __forceinline__ float sigf(float x) { return 1.0f / (1.0f + __expf(-x)); }

__device__ __forceinline__ unsigned smem_u32(const void* p) {
    return (unsigned)__cvta_generic_to_shared(p);
}
__device__ __forceinline__ void ldsm4(unsigned* r, unsigned addr) {
    asm volatile("ldmatrix.sync.aligned.m8n8.x4.shared.b16 {%0,%1,%2,%3}, [%4];"
                 : "=r"(r[0]), "=r"(r[1]), "=r"(r[2]), "=r"(r[3]) : "r"(addr));
}
__device__ __forceinline__ void mma16816(float* d, const unsigned* a, const unsigned* b) {
    asm volatile("mma.sync.aligned.m16n8k16.row.col.f32.f16.f16.f32 "
                 "{%0,%1,%2,%3}, {%4,%5,%6,%7}, {%8,%9}, {%0,%1,%2,%3};"
                 : "+f"(d[0]), "+f"(d[1]), "+f"(d[2]), "+f"(d[3])
                 : "r"(a[0]), "r"(a[1]), "r"(a[2]), "r"(a[3]), "r"(b[0]), "r"(b[1]));
}
__device__ __forceinline__ void cpasync16(unsigned saddr, const void* g) {
    asm volatile("cp.async.cg.shared.global [%0], [%1], 16;" :: "r"(saddr), "l"(g));
}
__device__ __forceinline__ void cpcommit() { asm volatile("cp.async.commit_group;" ::: "memory"); }
template<int N> __device__ __forceinline__ void cpwait() {
    asm volatile("cp.async.wait_group %0;" :: "n"(N) : "memory");
}
__device__ __forceinline__ unsigned pk_h2(float a, float b) {
    return (unsigned)__half_as_ushort(__float2half_rn(a))
         | ((unsigned)__half_as_ushort(__float2half_rn(b)) << 16);
}

// ---------------------------------------------------------------------------
// k_foldw: permute + fold weights into per-block slice tiles (fp16 hi/lo*4096)
// Slice row rr: gate=rr>>3, unit=rr&7 -> j = gate*1024 + blk*8 + unit.
// Plane layout (64KB): off = (k>>4)*1024 + ((gate*2)+((k>>3)&1))*128 + unit*16 + (k&7)*2
// ---------------------------------------------------------------------------
__global__ void k_foldw(const float* __restrict__ Wih, const float* __restrict__ Whh) {
    int i = blockIdx.x * blockDim.x + threadIdx.x;   // 4,194,304
    int k = i & 1023, rr = (i >> 10) & 31, blk = i >> 15;
    int gate = rr >> 3, unit = rr & 7;
    int j = (gate << 10) + (blk << 3) + unit;
    float a = Wih[(size_t)j * HH + k];
    float b = Whh[(size_t)j * HH + k];
    float f = a + b;
    int off = ((k >> 4) << 10) + (((gate << 1) + ((k >> 3) & 1)) << 7) + (unit << 4) + ((k & 7) << 1);
    unsigned char* bF = g_WswF + (size_t)blk * 131072;
    unsigned char* b0 = g_Wsw0 + (size_t)blk * 131072;
    __half fh = __float2half_rn(f);
    __half fl = __float2half_rn((f - __half2float(fh)) * 4096.0f);
    *(__half*)(bF + off)         = fh;
    *(__half*)(bF + 65536 + off) = fl;
    __half wh = __float2half_rn(b);
    __half wl = __float2half_rn((b - __half2float(wh)) * 4096.0f);
    *(__half*)(b0 + off)         = wh;
    *(__half*)(b0 + 65536 + off) = wl;
}

// W_out -> [nb(16)][ch(16)] 16KB blocks: hi 8KB [ck4][nt*2+kt][8x128B] then lo*4096 8KB
__global__ void k_foldo(const float* __restrict__ Wout) {
    int i = blockIdx.x * blockDim.x + threadIdx.x;   // 1,048,576
    int k = i & 1023, o = i >> 10;
    int nb = o >> 6, nt = (o >> 3) & 7, r = o & 7;
    int ch = k >> 6, ck4 = (k >> 4) & 3, kt = (k >> 3) & 1, c = k & 7;
    unsigned char* base = g_WoT + (size_t)(nb * 16 + ch) * 16384;
    int toff = (ck4 << 11) + (((nt << 1) + kt) << 7) + (r << 4) + (c << 1);
    float w = Wout[(size_t)o * HH + k];
    __half hi = __float2half_rn(w);
    __half lo = __float2half_rn((w - __half2float(hi)) * 4096.0f);
    *(__half*)(base + toff)        = hi;
    *(__half*)(base + 8192 + toff) = lo;
}

// bias fold (perm order r = gate*8+unit per blk)
__global__ void k_bias(const float* __restrict__ Wih, const float* __restrict__ bih,
                       const float* __restrict__ bhh, const float* __restrict__ x0) {
    int w    = (blockIdx.x * blockDim.x + threadIdx.x) >> 5;
    int lane = threadIdx.x & 31;
    if (w >= G4) return;
    int blk = w >> 5, lr = w & 31;
    int j   = (blk << 3) + (lr & 7) + ((lr >> 3) << 10);
    float s = 0.f;
    for (int k = lane; k < HH; k += 32) s += x0[k] * Wih[(size_t)j * HH + k];
    #pragma unroll
    for (int off = 16; off; off >>= 1) s += __shfl_down_sync(0xffffffffu, s, off);
    if (lane == 0) {
        float bf = bih[j] + bhh[j];
        g_bF[w] = bf;
        g_b0[w] = bf + s;
    }
}

// h0 (fp16, tiled) -> g_hT slot 0 ; c0 -> g_c0.  64 blocks x 16 u each; smem-tiled.
__global__ void __launch_bounds__(256) k_init(const float* __restrict__ z,
                       const float* __restrict__ Wh, const float* __restrict__ bh,
                       const float* __restrict__ Wc, const float* __restrict__ bc) {
    __shared__ float zs[128][33];
    __shared__ float Whs[16][33];
    __shared__ float Wcs[16][33];
    const int tid = threadIdx.x, bb = blockIdx.x;
    const int b = tid & 127, ug = tid >> 7;
    float accH[8], accC[8];
    #pragma unroll
    for (int j = 0; j < 8; ++j) { accH[j] = 0.f; accC[j] = 0.f; }

    for (int kc = 0; kc < 16; ++kc) {
        #pragma unroll
        for (int tq = 0; tq < 16; ++tq) {
            int idx = tid + tq * 256;                 // 4096 z elements
            int br = idx >> 5, kk = idx & 31;
            zs[br][kk] = z[br * DIN + kc * 32 + kk];
        }
        #pragma unroll
        for (int tq = 0; tq < 2; ++tq) {
            int idx = tid + tq * 256;                 // 512 W elements each
            int ur = idx >> 5, kk = idx & 31;
            Whs[ur][kk] = Wh[(size_t)(bb * 16 + ur) * DIN + kc * 32 + kk];
            Wcs[ur][kk] = Wc[(size_t)(bb * 16 + ur) * DIN + kc * 32 + kk];
        }
        __syncthreads();
        #pragma unroll 8
        for (int kk = 0; kk < 32; ++kk) {
            float zv = zs[b][kk];
            #pragma unroll
            for (int j = 0; j < 8; ++j) {
                accH[j] += zv * Whs[ug * 8 + j][kk];
                accC[j] += zv * Wcs[ug * 8 + j][kk];
            }
        }
        __syncthreads();
    }

    #pragma unroll
    for (int j = 0; j < 8; ++j) {
        int u = bb * 16 + ug * 8 + j;
        float hv = accH[j] + bh[u];
        int ck = u >> 6, C = u & 63;
        int off = (((b >> 3) << 3) + (C >> 3)) * 128 + ((b & 7) << 4) + ((C & 7) << 1);
        *(__half*)(g_hT + (size_t)ck * 16384 + off) = __float2half_rn(hv);
        g_c0[b * HH + u] = accC[j] + bc[u];
    }
}

// ---------------------------------------------------------------------------
// Persistent HMMA recurrence. 128 CTAs x 8 warps. W slice resident in SMEM.
// h staged via cp.async (fp16, pre-tiled in gmem), 4-deep ring.
// SMEM: [0..128) b0s [128..256) bFs | 1024 W_hi 64K | 66560 W_lo 64K |
//       A ring: 132096 + i*16384, i=0..3
// ---------------------------------------------------------------------------
#define S_WHI 1024
#define S_WLO 66560
#define S_TOT 197632

__global__ void __launch_bounds__(NTHR, 1) k_steps_mma() {
    extern __shared__ unsigned char sm[];
    const unsigned sb = smem_u32(sm);
    const int tid = threadIdx.x, blk = blockIdx.x;
    const int w = tid >> 5, lane = tid & 31;
    const int q = lane & 3, gr = lane >> 2, ls = lane >> 3;
    float* b0s = (float*)(sm);
    float* bFs = (float*)(sm + 128);

    if (tid < 32) {
        b0s[tid] = g_b0[blk * 32 + tid];
        bFs[tid] = g_bF[blk * 32 + tid];
    }
    {   // W slices for step 0 (W_hh only)
        const uint4* src = (const uint4*)(g_Wsw0 + (size_t)blk * 131072);
        uint4* dst = (uint4*)(sm + S_WHI);
        for (int i = tid; i < 8192; i += NTHR) dst[i] = src[i];
    }
    float cst[2][2];
    {
        int m0 = (w << 4) + gr;
        float2 v0 = *(const float2*)(g_c0 + m0 * HH + (blk << 3) + (q << 1));
        float2 v1 = *(const float2*)(g_c0 + (m0 + 8) * HH + (blk << 3) + (q << 1));
        cst[0][0] = v0.x; cst[0][1] = v0.y;
        cst[1][0] = v1.x; cst[1][1] = v1.y;
    }
    __syncthreads();

    const unsigned aBase = (unsigned)(((w * 2 + (ls & 1)) * 8 + (ls >> 1)) * 128 + (lane & 7) * 16);
    const unsigned bBase = (unsigned)((((ls >> 1) * 2 + (ls & 1)) * 128) + (lane & 7) * 16);
    const int cpo = tid * 16;
    unsigned bufs[4] = {sb + 132096u, sb + 148480u, sb + 164864u, sb + 181248u};

    for (int t = 0; t < TT; ++t) {
        const unsigned char* hsrc = g_hT + (size_t)t * SLOT;

        // prologue: issue chunks 0,1,2
        #pragma unroll
        for (int c = 0; c < 3; ++c) {
            const unsigned char* src = hsrc + (size_t)c * 16384;
            #pragma unroll
            for (int j = 0; j < 4; ++j) cpasync16(bufs[c] + cpo + j * 4096, src + cpo + j * 4096);
            cpcommit();
        }

        float accH[4][4], accL[4][4];
        #pragma unroll
        for (int a = 0; a < 4; ++a)
            #pragma unroll
            for (int b = 0; b < 4; ++b) { accH[a][b] = 0.f; accL[a][b] = 0.f; }

        for (int i = 0; i < 16; ++i) {
            if (i <= 13) cpwait<2>(); else if (i == 14) cpwait<1>(); else cpwait<0>();
            __syncthreads();
            if (i < 13) {   // prefetch chunk i+3 into freed buffer
                const unsigned char* src = hsrc + (size_t)(i + 3) * 16384;
                unsigned buf = bufs[(i + 3) & 3];
                #pragma unroll
                for (int j = 0; j < 4; ++j) cpasync16(buf + cpo + j * 4096, src + cpo + j * 4096);
                cpcommit();
            }
            unsigned cur = bufs[i & 3];
            #pragma unroll
            for (int kk = 0; kk < 4; ++kk) {
                unsigned Ah[4];
                ldsm4(Ah, cur + aBase + kk * 256);
                int ckk = i * 4 + kk;
                #pragma unroll
                for (int gg = 0; gg < 2; ++gg) {
                    unsigned Bh[4], Bl[4];
                    ldsm4(Bh, sb + S_WHI + ckk * 1024 + gg * 512 + bBase);
                    ldsm4(Bl, sb + S_WLO + ckk * 1024 + gg * 512 + bBase);
                    mma16816(accH[2 * gg],     Ah, Bh);
                    mma16816(accL[2 * gg],     Ah, Bl);
                    mma16816(accH[2 * gg + 1], Ah, Bh + 2);
                    mma16816(accL[2 * gg + 1], Ah, Bl + 2);
                }
            }
        }

        // epilogue: 4 gates of (b, u) live in this thread
        const float* bs = t ? bFs : b0s;
        unsigned char* hd = g_hT + (size_t)(t + 1) * SLOT + (size_t)(blk >> 3) * 16384;
        const int cb = blk & 7;
        #pragma unroll
        for (int r = 0; r < 2; ++r) {
            float hv[2];
            #pragma unroll
            for (int s = 0; s < 2; ++s) {
                int u = (q << 1) + s;
                int fi = r * 2 + s;
                float ig = accH[0][fi] + accL[0][fi] * INVS + bs[u];
                float fg = accH[1][fi] + accL[1][fi] * INVS + bs[8 + u];
                float gg = accH[2][fi] + accL[2][fi] * INVS + bs[16 + u];
                float og = accH[3][fi] + accL[3][fi] * INVS + bs[24 + u];
                float cn = sigf(fg) * cst[r][s] + sigf(ig) * tanhf(gg);
                cst[r][s] = cn;
                hv[s] = sigf(og) * tanhf(cn);
            }
            int toff = (((2 * w + r) << 3) + cb) * 128 + (gr << 4) + (q << 2);
            *(unsigned*)(hd + toff) = pk_h2(hv[0], hv[1]);
        }

        // global barrier (monotonic, replay-safe; all-thread fence -> release post)
        __threadfence();
        __syncthreads();
        if (tid == 0) {
            unsigned old;
            asm volatile("atom.release.gpu.global.add.u32 %0, [%1], %2;"
                         : "=r"(old) : "l"(&g_bar[t]), "r"(1u) : "memory");
            unsigned target = old - (old & (NBLK - 1)) + NBLK;
            unsigned v;
            do {
                asm volatile("ld.acquire.gpu.global.u32 %0, [%1];"
                             : "=r"(v) : "l"(&g_bar[t]) : "memory");
            } while ((int)(v - target) < 0);
        }
        __syncthreads();

        if (t == 0) {   // swap in folded weights for steps >= 1
            const uint4* src = (const uint4*)(g_WswF + (size_t)blk * 131072);
            uint4* dst = (uint4*)(sm + S_WHI);
            for (int i2 = tid; i2 < 8192; i2 += NTHR) dst[i2] = src[i2];
            __syncthreads();
        }
    }
}

// ---------------------------------------------------------------------------
// Output GEMM via cp.async staging. A fp16 single-plane from g_hT, B fp16
// hi/lo*4096 from g_WoT. 128x64 tiles, 2-deep ring (32KB/buf), occupancy 2.
// SMEM: bias 0..256 | buf0 1024 | buf1 33792  (A +0 16KB, B +16384 16KB)
// ---------------------------------------------------------------------------
#define KO_B0 1024
#define KO_B1 33792
#define SO_TOT 66560

__global__ void __launch_bounds__(256, 2) k_out_mma(const float* __restrict__ bout,
                                                    float* __restrict__ out) {
    extern __shared__ unsigned char sm[];
    const unsigned sb = smem_u32(sm);
    const int tid = threadIdx.x;
    const int w = tid >> 5, lane = tid & 31;
    const int q = lane & 3, gr = lane >> 2, ls = lane >> 3;
    const int nb = blockIdx.x, mb = blockIdx.y;
    float* bias_s = (float*)(sm);
    if (tid < 64) bias_s[tid] = bout[nb * 64 + tid];

    const unsigned aBase = (unsigned)(((w * 2 + (ls & 1)) * 8 + (ls >> 1)) * 128 + (lane & 7) * 16);
    const unsigned bBase = (unsigned)((((ls >> 1) * 2 + (ls & 1)) * 128) + (lane & 7) * 16);
    const int cpo = tid * 16;
    const unsigned char* Asrc = g_hT + (size_t)(mb + 1) * SLOT;
    const unsigned char* Bsrc = g_WoT + (size_t)nb * 16 * 16384;

    auto issue = [&](int ch, unsigned buf) {
        const unsigned char* a = Asrc + (size_t)ch * 16384;
        #pragma unroll
        for (int j = 0; j < 4; ++j) cpasync16(buf + cpo + j * 4096, a + cpo + j * 4096);
        const unsigned char* bsc = Bsrc + (size_t)ch * 16384;
        #pragma unroll
        for (int j = 0; j < 4; ++j) cpasync16(buf + 16384 + cpo + j * 4096, bsc + cpo + j * 4096);
        cpcommit();
    };

    unsigned cur = sb + KO_B0, oth = sb + KO_B1;
    issue(0, cur);
    issue(1, oth);

    float accH[8][4], accL[8][4];
    #pragma unroll
    for (int a = 0; a < 8; ++a)
        #pragma unroll
        for (int b = 0; b < 4; ++b) { accH[a][b] = 0.f; accL[a][b] = 0.f; }

    for (int i = 0; i < 16; ++i) {
        if (i < 15) cpwait<1>(); else cpwait<0>();
        __syncthreads();
        #pragma unroll
        for (int kk = 0; kk < 4; ++kk) {
            unsigned Ah[4];
            ldsm4(Ah, cur + aBase + kk * 256);
            #pragma unroll
            for (int gg = 0; gg < 4; ++gg) {
                unsigned Bh[4], Bl[4];
                ldsm4(Bh, cur + 16384 + kk * 2048 + gg * 512 + bBase);
                ldsm4(Bl, cur + 24576 + kk * 2048 + gg * 512 + bBase);
                mma16816(accH[2 * gg],     Ah, Bh);
                mma16816(accL[2 * gg],     Ah, Bl);
                mma16816(accH[2 * gg + 1], Ah, Bh + 2);
                mma16816(accL[2 * gg + 1], Ah, Bl + 2);
            }
        }
        __syncthreads();
        if (i < 14) issue(i + 2, cur);
        unsigned tmp = cur; cur = oth; oth = tmp;
    }

    // epilogue: combine hi/lo, bias + LeakyReLU, float2 stores
    #pragma unroll
    for (int nt = 0; nt < 8; ++nt) {
        int o0 = nb * 64 + nt * 8 + (q << 1);
        float bo0 = bias_s[nt * 8 + (q << 1)];
        float bo1 = bias_s[nt * 8 + (q << 1) + 1];
        #pragma unroll
        for (int r = 0; r < 2; ++r) {
            int m = mb * 128 + (w << 4) + gr + (r << 3);
            int tt = m >> 7, b = m & 127;
            float x0 = accH[nt][r * 2]     + accL[nt][r * 2]     * INVS + bo0;
            float x1 = accH[nt][r * 2 + 1] + accL[nt][r * 2 + 1] * INVS + bo1;
            float2 v;
            v.x = x0 >= 0.f ? x0 : 0.2f * x0;
            v.y = x1 >= 0.f ? x1 : 0.2f * x1;
            *(float2*)(out + (size_t)b * (TT * OO) + (size_t)tt * OO + o0) = v;
        }
    }
}

// ---------------------------------------------------------------------------
extern "C" void kernel_launch(void* const* d_in, const int* in_sizes, int n_in,
                              void* d_out, int out_size) {
    const float* z      = (const float*)d_in[0];
    const float* W_fc_h = (const float*)d_in[2];
    const float* b_fc_h = (const float*)d_in[3];
    const float* W_fc_c = (const float*)d_in[4];
    const float* b_fc_c = (const float*)d_in[5];
    const float* W_ih   = (const float*)d_in[6];
    const float* b_ih   = (const float*)d_in[7];
    const float* W_hh   = (const float*)d_in[8];
    const float* b_hh   = (const float*)d_in[9];
    const float* x0     = (const float*)d_in[10];
    const float* W_out  = (const float*)d_in[11];
    const float* b_out  = (const float*)d_in[12];
    float* out = (float*)d_out;

    k_foldw<<<16384, 256>>>(W_ih, W_hh);
    k_foldo<<<4096, 256>>>(W_out);
    k_bias<<<512, 256>>>(W_ih, b_ih, b_hh, x0);
    k_init<<<64, 256>>>(z, W_fc_h, b_fc_h, W_fc_c, b_fc_c);

    cudaFuncSetAttribute(k_steps_mma, cudaFuncAttributeMaxDynamicSharedMemorySize, S_TOT);
    k_steps_mma<<<NBLK, NTHR, S_TOT>>>();

    cudaFuncSetAttribute(k_out_mma, cudaFuncAttributeMaxDynamicSharedMemorySize, SO_TOT);
    k_out_mma<<<dim3(16, 256), 256, SO_TOT>>>(b_out, out);
}

// round 13
// speedup vs baseline: 5.1286x; 1.3275x over previous
#include <cuda_runtime.h>
#include <cuda_fp16.h>

#define Bb   128
#define DIN  512
#define HH   1024
#define G4   4096
#define TT   256
#define OO   1024
#define BH   (Bb*HH)
#define NBLK 128
#define NTHR 256
#define SLOT 262144   // per-step h slot: 16 chunks x 16KB (fp16 single plane)

// ---- device-global scratch ----
__device__ __align__(16) unsigned char g_hT[(TT+1)*SLOT];   // h history, tiled fp16
__device__ __align__(16) float         g_c0[BH];            // initial cell state
__device__ __align__(16) unsigned char g_WswF[NBLK*65536];  // folded slices, fp16 (t>=1)
__device__ __align__(16) unsigned char g_Wsw0[NBLK*65536];  // W_hh slices, fp16 (t==0)
__device__ __align__(16) unsigned char g_WoT[16*16*8192];   // W_out tiles, fp16
__device__ float    g_bF[G4];
__device__ float    g_b0[G4];
__device__ unsigned g_bar[TT];                              // monotonic barrier counters

__device__ __forceinline__ float sigf(float x) { return 1.0f / (1.0f + __expf(-x)); }

__device__ __forceinline__ unsigned smem_u32(const void* p) {
    return (unsigned)__cvta_generic_to_shared(p);
}
__device__ __forceinline__ void ldsm4(unsigned* r, unsigned addr) {
    asm volatile("ldmatrix.sync.aligned.m8n8.x4.shared.b16 {%0,%1,%2,%3}, [%4];"
                 : "=r"(r[0]), "=r"(r[1]), "=r"(r[2]), "=r"(r[3]) : "r"(addr));
}
__device__ __forceinline__ void mma16816(float* d, const unsigned* a, const unsigned* b) {
    asm volatile("mma.sync.aligned.m16n8k16.row.col.f32.f16.f16.f32 "
                 "{%0,%1,%2,%3}, {%4,%5,%6,%7}, {%8,%9}, {%0,%1,%2,%3};"
                 : "+f"(d[0]), "+f"(d[1]), "+f"(d[2]), "+f"(d[3])
                 : "r"(a[0]), "r"(a[1]), "r"(a[2]), "r"(a[3]), "r"(b[0]), "r"(b[1]));
}
__device__ __forceinline__ void cpasync16(unsigned saddr, const void* g) {
    asm volatile("cp.async.cg.shared.global [%0], [%1], 16;" :: "r"(saddr), "l"(g));
}
__device__ __forceinline__ void cpcommit() { asm volatile("cp.async.commit_group;" ::: "memory"); }
template<int N> __device__ __forceinline__ void cpwait() {
    asm volatile("cp.async.wait_group %0;" :: "n"(N) : "memory");
}
__device__ __forceinline__ unsigned pk_h2(float a, float b) {
    return (unsigned)__half_as_ushort(__float2half_rn(a))
         | ((unsigned)__half_as_ushort(__float2half_rn(b)) << 16);
}

// ---------------------------------------------------------------------------
// k_foldw: permute + fold weights into per-block slice tiles (fp16 single plane)
// Slice row rr: gate=rr>>3, unit=rr&7 -> j = gate*1024 + blk*8 + unit.
// Plane layout (64KB): off = (k>>4)*1024 + ((gate*2)+((k>>3)&1))*128 + unit*16 + (k&7)*2
// ---------------------------------------------------------------------------
__global__ void k_foldw(const float* __restrict__ Wih, const float* __restrict__ Whh) {
    int i = blockIdx.x * blockDim.x + threadIdx.x;   // 4,194,304
    int k = i & 1023, rr = (i >> 10) & 31, blk = i >> 15;
    int gate = rr >> 3, unit = rr & 7;
    int j = (gate << 10) + (blk << 3) + unit;
    float a = Wih[(size_t)j * HH + k];
    float b = Whh[(size_t)j * HH + k];
    int off = ((k >> 4) << 10) + (((gate << 1) + ((k >> 3) & 1)) << 7) + (unit << 4) + ((k & 7) << 1);
    *(__half*)(g_WswF + (size_t)blk * 65536 + off) = __float2half_rn(a + b);
    *(__half*)(g_Wsw0 + (size_t)blk * 65536 + off) = __float2half_rn(b);
}

// W_out -> [nb(16)][ch(16)] 8KB blocks: [ck4][nt*2+kt][8x16B], fp16
__global__ void k_foldo(const float* __restrict__ Wout) {
    int i = blockIdx.x * blockDim.x + threadIdx.x;   // 1,048,576
    int k = i & 1023, o = i >> 10;
    int nb = o >> 6, nt = (o >> 3) & 7, r = o & 7;
    int ch = k >> 6, ck4 = (k >> 4) & 3, kt = (k >> 3) & 1, c = k & 7;
    int toff = (ck4 << 11) + (((nt << 1) + kt) << 7) + (r << 4) + (c << 1);
    *(__half*)(g_WoT + (size_t)(nb * 16 + ch) * 8192 + toff) =
        __float2half_rn(Wout[(size_t)o * HH + k]);
}

// bias fold (perm order r = gate*8+unit per blk)
__global__ void k_bias(const float* __restrict__ Wih, const float* __restrict__ bih,
                       const float* __restrict__ bhh, const float* __restrict__ x0) {
    int w    = (blockIdx.x * blockDim.x + threadIdx.x) >> 5;
    int lane = threadIdx.x & 31;
    if (w >= G4) return;
    int blk = w >> 5, lr = w & 31;
    int j   = (blk << 3) + (lr & 7) + ((lr >> 3) << 10);
    float s = 0.f;
    for (int k = lane; k < HH; k += 32) s += x0[k] * Wih[(size_t)j * HH + k];
    #pragma unroll
    for (int off = 16; off; off >>= 1) s += __shfl_down_sync(0xffffffffu, s, off);
    if (lane == 0) {
        float bf = bih[j] + bhh[j];
        g_bF[w] = bf;
        g_b0[w] = bf + s;
    }
}

// h0 (fp16, tiled) -> g_hT slot 0 ; c0 -> g_c0.  64 blocks x 16 u each; smem-tiled.
__global__ void __launch_bounds__(256) k_init(const float* __restrict__ z,
                       const float* __restrict__ Wh, const float* __restrict__ bh,
                       const float* __restrict__ Wc, const float* __restrict__ bc) {
    __shared__ float zs[128][33];
    __shared__ float Whs[16][33];
    __shared__ float Wcs[16][33];
    const int tid = threadIdx.x, bb = blockIdx.x;
    const int b = tid & 127, ug = tid >> 7;
    float accH[8], accC[8];
    #pragma unroll
    for (int j = 0; j < 8; ++j) { accH[j] = 0.f; accC[j] = 0.f; }

    for (int kc = 0; kc < 16; ++kc) {
        #pragma unroll
        for (int tq = 0; tq < 16; ++tq) {
            int idx = tid + tq * 256;
            int br = idx >> 5, kk = idx & 31;
            zs[br][kk] = z[br * DIN + kc * 32 + kk];
        }
        #pragma unroll
        for (int tq = 0; tq < 2; ++tq) {
            int idx = tid + tq * 256;
            int ur = idx >> 5, kk = idx & 31;
            Whs[ur][kk] = Wh[(size_t)(bb * 16 + ur) * DIN + kc * 32 + kk];
            Wcs[ur][kk] = Wc[(size_t)(bb * 16 + ur) * DIN + kc * 32 + kk];
        }
        __syncthreads();
        #pragma unroll 8
        for (int kk = 0; kk < 32; ++kk) {
            float zv = zs[b][kk];
            #pragma unroll
            for (int j = 0; j < 8; ++j) {
                accH[j] += zv * Whs[ug * 8 + j][kk];
                accC[j] += zv * Wcs[ug * 8 + j][kk];
            }
        }
        __syncthreads();
    }

    #pragma unroll
    for (int j = 0; j < 8; ++j) {
        int u = bb * 16 + ug * 8 + j;
        float hv = accH[j] + bh[u];
        int ck = u >> 6, C = u & 63;
        int off = (((b >> 3) << 3) + (C >> 3)) * 128 + ((b & 7) << 4) + ((C & 7) << 1);
        *(__half*)(g_hT + (size_t)ck * 16384 + off) = __float2half_rn(hv);
        g_c0[b * HH + u] = accC[j] + bc[u];
    }
}

// ---------------------------------------------------------------------------
// Persistent HMMA recurrence. 128 CTAs x 8 warps. fp16 W slice (64KB) in SMEM.
// h staged via cp.async (fp16, pre-tiled in gmem), 4-deep ring.
// SMEM: [0..128) b0s [128..256) bFs | 1024 W 64K | A ring 66560 + i*16384
// ---------------------------------------------------------------------------
#define S_W   1024
#define S_TOT 132096

__global__ void __launch_bounds__(NTHR, 1) k_steps_mma() {
    extern __shared__ unsigned char sm[];
    const unsigned sb = smem_u32(sm);
    const int tid = threadIdx.x, blk = blockIdx.x;
    const int w = tid >> 5, lane = tid & 31;
    const int q = lane & 3, gr = lane >> 2, ls = lane >> 3;
    float* b0s = (float*)(sm);
    float* bFs = (float*)(sm + 128);

    if (tid < 32) {
        b0s[tid] = g_b0[blk * 32 + tid];
        bFs[tid] = g_bF[blk * 32 + tid];
    }
    {   // W slice for step 0 (W_hh only)
        const uint4* src = (const uint4*)(g_Wsw0 + (size_t)blk * 65536);
        uint4* dst = (uint4*)(sm + S_W);
        for (int i = tid; i < 4096; i += NTHR) dst[i] = src[i];
    }
    float cst[2][2];
    {
        int m0 = (w << 4) + gr;
        float2 v0 = *(const float2*)(g_c0 + m0 * HH + (blk << 3) + (q << 1));
        float2 v1 = *(const float2*)(g_c0 + (m0 + 8) * HH + (blk << 3) + (q << 1));
        cst[0][0] = v0.x; cst[0][1] = v0.y;
        cst[1][0] = v1.x; cst[1][1] = v1.y;
    }
    __syncthreads();

    const unsigned aBase = (unsigned)(((w * 2 + (ls & 1)) * 8 + (ls >> 1)) * 128 + (lane & 7) * 16);
    const unsigned bBase = (unsigned)((((ls >> 1) * 2 + (ls & 1)) * 128) + (lane & 7) * 16);
    const int cpo = tid * 16;
    unsigned bufs[4] = {sb + 66560u, sb + 82944u, sb + 99328u, sb + 115712u};

    for (int t = 0; t < TT; ++t) {
        const unsigned char* hsrc = g_hT + (size_t)t * SLOT;

        // prologue: issue chunks 0,1,2
        #pragma unroll
        for (int c = 0; c < 3; ++c) {
            const unsigned char* src = hsrc + (size_t)c * 16384;
            #pragma unroll
            for (int j = 0; j < 4; ++j) cpasync16(bufs[c] + cpo + j * 4096, src + cpo + j * 4096);
            cpcommit();
        }

        float acc[4][4];
        #pragma unroll
        for (int a = 0; a < 4; ++a)
            #pragma unroll
            for (int b = 0; b < 4; ++b) acc[a][b] = 0.f;

        for (int i = 0; i < 16; ++i) {
            if (i <= 13) cpwait<2>(); else if (i == 14) cpwait<1>(); else cpwait<0>();
            __syncthreads();
            if (i < 13) {   // prefetch chunk i+3 into freed buffer
                const unsigned char* src = hsrc + (size_t)(i + 3) * 16384;
                unsigned buf = bufs[(i + 3) & 3];
                #pragma unroll
                for (int j = 0; j < 4; ++j) cpasync16(buf + cpo + j * 4096, src + cpo + j * 4096);
                cpcommit();
            }
            unsigned cur = bufs[i & 3];
            #pragma unroll
            for (int kk = 0; kk < 4; ++kk) {
                unsigned Ah[4];
                ldsm4(Ah, cur + aBase + kk * 256);
                int ckk = i * 4 + kk;
                #pragma unroll
                for (int gg = 0; gg < 2; ++gg) {
                    unsigned Bh[4];
                    ldsm4(Bh, sb + S_W + ckk * 1024 + gg * 512 + bBase);
                    mma16816(acc[2 * gg],     Ah, Bh);
                    mma16816(acc[2 * gg + 1], Ah, Bh + 2);
                }
            }
        }

        // epilogue: 4 gates of (b, u) live in this thread
        const float* bs = t ? bFs : b0s;
        unsigned char* hd = g_hT + (size_t)(t + 1) * SLOT + (size_t)(blk >> 3) * 16384;
        const int cb = blk & 7;
        #pragma unroll
        for (int r = 0; r < 2; ++r) {
            float hv[2];
            #pragma unroll
            for (int s = 0; s < 2; ++s) {
                int u = (q << 1) + s;
                int fi = r * 2 + s;
                float ig = acc[0][fi] + bs[u];
                float fg = acc[1][fi] + bs[8 + u];
                float gg = acc[2][fi] + bs[16 + u];
                float og = acc[3][fi] + bs[24 + u];
                float cn = sigf(fg) * cst[r][s] + sigf(ig) * tanhf(gg);
                cst[r][s] = cn;
                hv[s] = sigf(og) * tanhf(cn);
            }
            int toff = (((2 * w + r) << 3) + cb) * 128 + (gr << 4) + (q << 2);
            *(unsigned*)(hd + toff) = pk_h2(hv[0], hv[1]);
        }

        // global barrier (monotonic, replay-safe; all-thread fence -> release post)
        __threadfence();
        __syncthreads();
        if (tid == 0) {
            unsigned old;
            asm volatile("atom.release.gpu.global.add.u32 %0, [%1], %2;"
                         : "=r"(old) : "l"(&g_bar[t]), "r"(1u) : "memory");
            unsigned target = old - (old & (NBLK - 1)) + NBLK;
            unsigned v;
            do {
                asm volatile("ld.acquire.gpu.global.u32 %0, [%1];"
                             : "=r"(v) : "l"(&g_bar[t]) : "memory");
            } while ((int)(v - target) < 0);
        }
        __syncthreads();

        if (t == 0) {   // swap in folded weights for steps >= 1
            const uint4* src = (const uint4*)(g_WswF + (size_t)blk * 65536);
            uint4* dst = (uint4*)(sm + S_W);
            for (int i2 = tid; i2 < 4096; i2 += NTHR) dst[i2] = src[i2];
            __syncthreads();
        }
    }
}

// ---------------------------------------------------------------------------
// Output GEMM via cp.async staging. A fp16 from g_hT, B fp16 from g_WoT.
// 128x64 tiles, 2-deep ring (24KB/buf), occupancy 2.
// SMEM: bias 0..256 | buf0 1024 | buf1 25600  (A +0 16KB, B +16384 8KB)
// ---------------------------------------------------------------------------
#define KO_B0 1024
#define KO_B1 25600
#define SO_TOT 50176

__global__ void __launch_bounds__(256, 2) k_out_mma(const float* __restrict__ bout,
                                                    float* __restrict__ out) {
    extern __shared__ unsigned char sm[];
    const unsigned sb = smem_u32(sm);
    const int tid = threadIdx.x;
    const int w = tid >> 5, lane = tid & 31;
    const int q = lane & 3, gr = lane >> 2, ls = lane >> 3;
    const int nb = blockIdx.x, mb = blockIdx.y;
    float* bias_s = (float*)(sm);
    if (tid < 64) bias_s[tid] = bout[nb * 64 + tid];

    const unsigned aBase = (unsigned)(((w * 2 + (ls & 1)) * 8 + (ls >> 1)) * 128 + (lane & 7) * 16);
    const unsigned bBase = (unsigned)((((ls >> 1) * 2 + (ls & 1)) * 128) + (lane & 7) * 16);
    const int cpo = tid * 16;
    const int cpo2 = tid * 32;   // B chunk: 8KB over 256 threads = 32B each
    const unsigned char* Asrc = g_hT + (size_t)(mb + 1) * SLOT;
    const unsigned char* Bsrc = g_WoT + (size_t)nb * 16 * 8192;

    auto issue = [&](int ch, unsigned buf) {
        const unsigned char* a = Asrc + (size_t)ch * 16384;
        #pragma unroll
        for (int j = 0; j < 4; ++j) cpasync16(buf + cpo + j * 4096, a + cpo + j * 4096);
        const unsigned char* bsc = Bsrc + (size_t)ch * 8192;
        cpasync16(buf + 16384 + cpo2,      bsc + cpo2);
        cpasync16(buf + 16384 + cpo2 + 16, bsc + cpo2 + 16);
        cpcommit();
    };

    unsigned cur = sb + KO_B0, oth = sb + KO_B1;
    issue(0, cur);
    issue(1, oth);

    float acc[8][4];
    #pragma unroll
    for (int a = 0; a < 8; ++a)
        #pragma unroll
        for (int b = 0; b < 4; ++b) acc[a][b] = 0.f;

    for (int i = 0; i < 16; ++i) {
        if (i < 15) cpwait<1>(); else cpwait<0>();
        __syncthreads();
        #pragma unroll
        for (int kk = 0; kk < 4; ++kk) {
            unsigned Ah[4];
            ldsm4(Ah, cur + aBase + kk * 256);
            #pragma unroll
            for (int gg = 0; gg < 4; ++gg) {
                unsigned Bh[4];
                ldsm4(Bh, cur + 16384 + kk * 2048 + gg * 512 + bBase);
                mma16816(acc[2 * gg],     Ah, Bh);
                mma16816(acc[2 * gg + 1], Ah, Bh + 2);
            }
        }
        __syncthreads();
        if (i < 14) issue(i + 2, cur);
        unsigned tmp = cur; cur = oth; oth = tmp;
    }

    // epilogue: bias + LeakyReLU, float2 stores
    #pragma unroll
    for (int nt = 0; nt < 8; ++nt) {
        int o0 = nb * 64 + nt * 8 + (q << 1);
        float bo0 = bias_s[nt * 8 + (q << 1)];
        float bo1 = bias_s[nt * 8 + (q << 1) + 1];
        #pragma unroll
        for (int r = 0; r < 2; ++r) {
            int m = mb * 128 + (w << 4) + gr + (r << 3);
            int tt = m >> 7, b = m & 127;
            float x0 = acc[nt][r * 2]     + bo0;
            float x1 = acc[nt][r * 2 + 1] + bo1;
            float2 v;
            v.x = x0 >= 0.f ? x0 : 0.2f * x0;
            v.y = x1 >= 0.f ? x1 : 0.2f * x1;
            *(float2*)(out + (size_t)b * (TT * OO) + (size_t)tt * OO + o0) = v;
        }
    }
}

// ---------------------------------------------------------------------------
extern "C" void kernel_launch(void* const* d_in, const int* in_sizes, int n_in,
                              void* d_out, int out_size) {
    const float* z      = (const float*)d_in[0];
    const float* W_fc_h = (const float*)d_in[2];
    const float* b_fc_h = (const float*)d_in[3];
    const float* W_fc_c = (const float*)d_in[4];
    const float* b_fc_c = (const float*)d_in[5];
    const float* W_ih   = (const float*)d_in[6];
    const float* b_ih   = (const float*)d_in[7];
    const float* W_hh   = (const float*)d_in[8];
    const float* b_hh   = (const float*)d_in[9];
    const float* x0     = (const float*)d_in[10];
    const float* W_out  = (const float*)d_in[11];
    const float* b_out  = (const float*)d_in[12];
    float* out = (float*)d_out;

    k_foldw<<<16384, 256>>>(W_ih, W_hh);
    k_foldo<<<4096, 256>>>(W_out);
    k_bias<<<512, 256>>>(W_ih, b_ih, b_hh, x0);
    k_init<<<64, 256>>>(z, W_fc_h, b_fc_h, W_fc_c, b_fc_c);

    cudaFuncSetAttribute(k_steps_mma, cudaFuncAttributeMaxDynamicSharedMemorySize, S_TOT);
    k_steps_mma<<<NBLK, NTHR, S_TOT>>>();

    cudaFuncSetAttribute(k_out_mma, cudaFuncAttributeMaxDynamicSharedMemorySize, SO_TOT);
    k_out_mma<<<dim3(16, 256), 256, SO_TOT>>>(b_out, out);
}